// round 9
// baseline (speedup 1.0000x reference)
#include <cuda_runtime.h>
#include <cstdint>
#include <math.h>

// Problem constants
constexpr int cB   = 32;
constexpr int cN   = 256;
constexpr int cCIN = 64;
constexpr int cCH  = 128;   // C_H == C_OUT
constexpr int cR   = 5;
constexpr int cJR  = cN * cR;       // 1280
constexpr int cJQ  = cJR / 4;       // 320 per quarter
constexpr int cXD  = 1024;

constexpr int MASK_WORDS_PER_ROW = cJR / 32;  // 40
constexpr int MASK_WORDS_Q      = cJQ / 32;   // 10
constexpr int ATTN_TILE_I = 32;                // i-rows per tile
constexpr int N_ITILES = cN / ATTN_TILE_I;     // 8
constexpr int P_STRIDE = 36;                   // padded stride of s_p [jr_local][row]
constexpr int TILE_JR = 16;                    // H rows per stage
constexpr int N_STAGES = 3;
constexpr int N_TILES_Q = cJQ / TILE_JR;       // 20

// smem floats: s_p 320*36 + s_dst 320 + s_src 160 + s_h 3*16*128
constexpr int ATTN_SMEM = (cJQ * P_STRIDE + cJQ + ATTN_TILE_I * cR
                           + N_STAGES * TILE_JR * cCH) * 4;   // 72,576 B -> 3 blocks/SM

// ---------------- device scratch (no cudaMalloc allowed) ----------------
__device__ float    g_h[cB * cN * cR * cCH];            // (b, jr, c): 8192 x 640
__device__ float    g_atoms[cB * cN * cCH];             // layer activations (b,n,c)
__device__ float    g_src[cB * cN * cR];
__device__ float    g_dst[cB * cN * cR];
__device__ unsigned g_mask[cB * cN * MASK_WORDS_PER_ROW];
__device__ float    g_part[cB * N_ITILES * 4 * ATTN_TILE_I * cCH];  // 16 MB partial S
__device__ float    g_psum[cB * N_ITILES * 4 * ATTN_TILE_I];        // partial sums
__device__ int      g_cnt[cB * N_ITILES];               // arrival counters (mod-4 used)
__device__ float    g_pool[cB * 2 * cCH];               // [mean(128) | max(128)] per batch

__device__ __forceinline__ float leaky(float v) { return v >= 0.f ? v : 0.2f * v; }

__device__ __forceinline__ void cp_async16(unsigned int smem_dst, const void* gsrc) {
    asm volatile("cp.async.cg.shared.global [%0], [%1], 16;\n" :: "r"(smem_dst), "l"(gsrc));
}
__device__ __forceinline__ void cp_commit() {
    asm volatile("cp.async.commit_group;\n");
}
template <int N>
__device__ __forceinline__ void cp_wait() {
    asm volatile("cp.async.wait_group %0;\n" :: "n"(N));
}

// packed f32x2 helpers (Blackwell FFMA2 path — PTX only)
__device__ __forceinline__ unsigned long long pack2(float lo, float hi) {
    unsigned long long r;
    asm("mov.b64 %0, {%1, %2};" : "=l"(r) : "f"(lo), "f"(hi));
    return r;
}
__device__ __forceinline__ void fma2(unsigned long long& d, unsigned long long a,
                                     unsigned long long b) {
    asm("fma.rn.f32x2 %0, %1, %2, %0;" : "+l"(d) : "l"(a), "l"(b));
}
__device__ __forceinline__ float2 unpack2(unsigned long long v) {
    float2 r;
    asm("mov.b64 {%0, %1}, %2;" : "=f"(r.x), "=f"(r.y) : "l"(v));
    return r;
}

// ---------------- 1) pack bond mask into bits ----------------
__global__ __launch_bounds__(256) void pack_mask_kernel(const int* __restrict__ bonds) {
    int w = blockIdx.x * blockDim.x + threadIdx.x;
    if (w >= cB * cN * MASK_WORDS_PER_ROW) return;
    const int4* p = reinterpret_cast<const int4*>(bonds) + w * 8;
    unsigned m = 0;
#pragma unroll
    for (int q = 0; q < 8; q++) {
        int4 v = p[q];
        m |= (v.x == 1 ? 1u : 0u) << (q * 4 + 0);
        m |= (v.y == 1 ? 1u : 0u) << (q * 4 + 1);
        m |= (v.z == 1 ? 1u : 0u) << (q * 4 + 2);
        m |= (v.w == 1 ? 1u : 0u) << (q * 4 + 3);
    }
    g_mask[w] = m;
}

// ---------------- 2) h = A @ W + bias   (M=8192, N=640, K=64/128) ----------------
template <int K>
__global__ __launch_bounds__(256) void gemm_bias_kernel(const float* __restrict__ A,
                                                        const float* __restrict__ W,
                                                        const float* __restrict__ bias) {
    __shared__ float As[16][64];
    __shared__ float Bs[16][64];
    const int t  = threadIdx.x;
    const int tx = t & 15, ty = t >> 4;
    const int bm = blockIdx.y * 64, bn = blockIdx.x * 64;

    unsigned long long accp[4][2];
#pragma unroll
    for (int i = 0; i < 4; i++) { accp[i][0] = 0ull; accp[i][1] = 0ull; }

    const int arow = t >> 2, akq = t & 3;
    const int bkr = t >> 4, bn4 = t & 15;

    for (int bk = 0; bk < K; bk += 16) {
        float4 av = *reinterpret_cast<const float4*>(&A[(bm + arow) * K + bk + akq * 4]);
        As[akq * 4 + 0][arow] = av.x;
        As[akq * 4 + 1][arow] = av.y;
        As[akq * 4 + 2][arow] = av.z;
        As[akq * 4 + 3][arow] = av.w;
        *reinterpret_cast<float4*>(&Bs[bkr][bn4 * 4]) =
            *reinterpret_cast<const float4*>(&W[(bk + bkr) * 640 + bn + bn4 * 4]);
        __syncthreads();
#pragma unroll
        for (int k = 0; k < 16; k++) {
            float4 a  = *reinterpret_cast<float4*>(&As[k][ty * 4]);
            float4 bv = *reinterpret_cast<float4*>(&Bs[k][tx * 4]);
            unsigned long long b01 = pack2(bv.x, bv.y), b23 = pack2(bv.z, bv.w);
            unsigned long long pa;
            pa = pack2(a.x, a.x); fma2(accp[0][0], pa, b01); fma2(accp[0][1], pa, b23);
            pa = pack2(a.y, a.y); fma2(accp[1][0], pa, b01); fma2(accp[1][1], pa, b23);
            pa = pack2(a.z, a.z); fma2(accp[2][0], pa, b01); fma2(accp[2][1], pa, b23);
            pa = pack2(a.w, a.w); fma2(accp[3][0], pa, b01); fma2(accp[3][1], pa, b23);
        }
        __syncthreads();
    }
    float4 bb = *reinterpret_cast<const float4*>(&bias[bn + tx * 4]);
#pragma unroll
    for (int i = 0; i < 4; i++) {
        float2 lo = unpack2(accp[i][0]), hi = unpack2(accp[i][1]);
        float4 o;
        o.x = lo.x + bb.x; o.y = lo.y + bb.y;
        o.z = hi.x + bb.z; o.w = hi.y + bb.w;
        *reinterpret_cast<float4*>(&g_h[(bm + ty * 4 + i) * 640 + bn + tx * 4]) = o;
    }
}

// ---------------- 3) src/dst projections ----------------
__global__ __launch_bounds__(160) void src_dst_kernel(const float* __restrict__ a) {
    const int bn   = blockIdx.x;
    const int r    = threadIdx.x >> 5;
    const int lane = threadIdx.x & 31;
    const float* hrow = &g_h[((size_t)bn * cR + r) * cCH];
    float4 hv = *reinterpret_cast<const float4*>(&hrow[lane * 4]);
    float4 as = *reinterpret_cast<const float4*>(&a[r * (2 * cCH) + lane * 4]);
    float4 ad = *reinterpret_cast<const float4*>(&a[r * (2 * cCH) + cCH + lane * 4]);
    float s = hv.x * as.x + hv.y * as.y + hv.z * as.z + hv.w * as.w;
    float d = hv.x * ad.x + hv.y * ad.y + hv.z * ad.z + hv.w * ad.w;
#pragma unroll
    for (int o = 16; o; o >>= 1) {
        s += __shfl_xor_sync(0xffffffffu, s, o);
        d += __shfl_xor_sync(0xffffffffu, d, o);
    }
    if (lane == 0) {
        g_src[bn * cR + r] = s;
        g_dst[bn * cR + r] = d;
    }
}

// ---------------- 4) attention partial + inline combine ----------------
// blockIdx.x = ((b*8 + itile) << 2) | quarter.  Each block: 32 rows x 320 jr.
// p = mask ? exp(leaky(src+dst)) : 0 (no max-sub; logits O(1), validated R7/R8).
// Phase 2 = R5 tiling, 3-stage cp.async ring, 1 barrier per 16-jr tile.
// Partial S + row-sums go to global; the LAST arriving quarter (atomic counter)
// combines all 4 in fixed q order, normalizes, applies leaky, writes g_atoms.
template <bool LEAKY_OUT>
__global__ __launch_bounds__(256) void attn_part_kernel() {
    extern __shared__ float sm[];
    float* s_p   = sm;                         // [320][36] transposed (jr_local, row)
    float* s_dst = s_p + cJQ * P_STRIDE;       // 320
    float* s_src = s_dst + cJQ;                // 160
    float* s_h   = s_src + ATTN_TILE_I * cR;   // 3*16*128 (16B aligned)
    __shared__ int s_last;

    const int blk   = blockIdx.x;
    const int q     = blk & 3;
    const int cidx  = blk >> 2;                // b*8 + itile
    const int itile = cidx & 7;
    const int b     = blk >> 5;
    const int i0    = itile * ATTN_TILE_I;
    const int t     = threadIdx.x;

    const float* hbase = &g_h[((size_t)b * cJR + q * cJQ) * cCH];
    const unsigned s_h_addr = (unsigned)__cvta_generic_to_shared(s_h);

    // prefetch tiles 0,1 (16x128 floats each = 2 cp_async16 per thread)
#pragma unroll
    for (int tile = 0; tile < 2; tile++) {
        const float* src = hbase + tile * TILE_JR * cCH;
        unsigned dst = s_h_addr + tile * (TILE_JR * cCH * 4);
#pragma unroll
        for (int u = 0; u < 2; u++) {
            int idx = t + 256 * u;
            int r = idx >> 5, c4 = idx & 31;
            cp_async16(dst + (r * cCH + c4 * 4) * 4, src + r * cCH + c4 * 4);
        }
        cp_commit();
    }

    for (int idx = t; idx < cJQ; idx += 256) s_dst[idx] = g_dst[b * cJR + q * cJQ + idx];
    if (t < ATTN_TILE_I * cR) s_src[t] = g_src[(b * cN + i0) * cR + t];
    __syncthreads();

    // ---- phase 1 (8 threads / row): p = mask ? exp(leaky(src+dst)) : 0
    {
        const int row = t >> 3, l8 = t & 7;
        const float* srcr = s_src + row * cR;
        const unsigned* mrow = &g_mask[(b * cN + i0 + row) * MASK_WORDS_PER_ROW
                                       + q * MASK_WORDS_Q];
        float sum = 0.f;
        int r = l8 % 5;                        // 320 % 5 == 0 so local e%5 == global jr%5
        for (int e = l8; e < cJQ; e += 8) {
            float v = leaky(srcr[r] + s_dst[e]);
            unsigned bit = (mrow[e >> 5] >> (e & 31)) & 1u;
            float p = bit ? __expf(v) : 0.f;
            s_p[e * P_STRIDE + row] = p;
            sum += p;
            r += 3; if (r >= 5) r -= 5;
        }
#pragma unroll
        for (int o = 4; o; o >>= 1) sum += __shfl_xor_sync(0xffffffffu, sum, o);
        if (l8 == 0) g_psum[blk * ATTN_TILE_I + row] = sum;
    }

    // ---- phase 2: S[32][128] = P_q @ H_q (unnormalized)
    const int c4 = t & 31;                     // cols c4*4..+3
    const int rg = t >> 5;                     // warp -> rows rg*4..+3
    {
        unsigned long long acc[4][2];
#pragma unroll
        for (int i = 0; i < 4; i++) { acc[i][0] = 0ull; acc[i][1] = 0ull; }

        const float* pbase = s_p + rg * 4;

        for (int tile = 0; tile < N_TILES_Q; tile++) {
            cp_wait<1>();
            __syncthreads();   // tile ready; compute of tile-1 done block-wide
            if (tile + 2 < N_TILES_Q) {
                unsigned stg = (tile + 2) % N_STAGES;
                const float* src = hbase + (tile + 2) * TILE_JR * cCH;
                unsigned dst = s_h_addr + stg * (TILE_JR * cCH * 4);
#pragma unroll
                for (int u = 0; u < 2; u++) {
                    int idx = t + 256 * u;
                    int r = idx >> 5, cc = idx & 31;
                    cp_async16(dst + (r * cCH + cc * 4) * 4, src + r * cCH + cc * 4);
                }
            }
            cp_commit();       // exactly one group per iteration

            const float* hh = s_h + (tile % N_STAGES) * (TILE_JR * cCH) + c4 * 4;
            const float* pp = pbase + tile * TILE_JR * P_STRIDE;
#pragma unroll
            for (int j = 0; j < TILE_JR; j++) {
                float4 p4 = *reinterpret_cast<const float4*>(pp);  // warp-uniform bcast
                ulonglong2 hv = *reinterpret_cast<const ulonglong2*>(hh);
                unsigned long long pa;
                pa = pack2(p4.x, p4.x); fma2(acc[0][0], pa, hv.x); fma2(acc[0][1], pa, hv.y);
                pa = pack2(p4.y, p4.y); fma2(acc[1][0], pa, hv.x); fma2(acc[1][1], pa, hv.y);
                pa = pack2(p4.z, p4.z); fma2(acc[2][0], pa, hv.x); fma2(acc[2][1], pa, hv.y);
                pa = pack2(p4.w, p4.w); fma2(acc[3][0], pa, hv.x); fma2(acc[3][1], pa, hv.y);
                pp += P_STRIDE;
                hh += cCH;
            }
        }

        float* outb = &g_part[(size_t)blk * ATTN_TILE_I * cCH];
#pragma unroll
        for (int i = 0; i < 4; i++) {
            float2 lo = unpack2(acc[i][0]), hi = unpack2(acc[i][1]);
            *reinterpret_cast<float4*>(&outb[(rg * 4 + i) * cCH + c4 * 4]) =
                make_float4(lo.x, lo.y, hi.x, hi.y);
        }
    }

    // ---- inline combine: last arriving quarter finalizes this (b, itile)
    __threadfence();
    __syncthreads();
    if (t == 0) s_last = (atomicAdd(&g_cnt[cidx], 1) & 3);
    __syncthreads();
    if (s_last == 3) {
        __threadfence();   // acquire: partials + psums of all quarters visible
        const float* base = &g_part[(size_t)cidx * 4 * ATTN_TILE_I * cCH];
        const float* psb  = &g_psum[cidx * 4 * ATTN_TILE_I];
#pragma unroll
        for (int i = 0; i < 4; i++) {
            const int row = rg * 4 + i;
            float s = ((psb[row] + psb[ATTN_TILE_I + row])
                     + (psb[2 * ATTN_TILE_I + row] + psb[3 * ATTN_TILE_I + row]));
            float inv = 1.f / s;
            float4 o = make_float4(0.f, 0.f, 0.f, 0.f);
#pragma unroll
            for (int qq = 0; qq < 4; qq++) {
                float4 v = *reinterpret_cast<const float4*>(
                    &base[(qq * ATTN_TILE_I + row) * cCH + c4 * 4]);
                o.x += v.x; o.y += v.y; o.z += v.z; o.w += v.w;
            }
            o.x *= inv; o.y *= inv; o.z *= inv; o.w *= inv;
            if (LEAKY_OUT) {
                o.x = leaky(o.x); o.y = leaky(o.y); o.z = leaky(o.z); o.w = leaky(o.w);
            }
            *reinterpret_cast<float4*>(&g_atoms[(b * cN + i0 + row) * cCH + c4 * 4]) = o;
        }
    }
}

// ---------------- 5) mean/max pooling over nodes ----------------
__global__ __launch_bounds__(512) void pool_kernel() {
    __shared__ float s_sum[4][cCH];
    __shared__ float s_max[4][cCH];
    const int b  = blockIdx.x;
    const int c  = threadIdx.x & 127;
    const int ch = threadIdx.x >> 7;
    float sum = 0.f, mx = -3.4e38f;
    for (int n = ch * 64; n < ch * 64 + 64; n++) {
        float v = g_atoms[(b * cN + n) * cCH + c];
        sum += v;
        mx = fmaxf(mx, v);
    }
    s_sum[ch][c] = sum;
    s_max[ch][c] = mx;
    __syncthreads();
    if (ch == 0) {
        sum = (s_sum[0][c] + s_sum[1][c]) + (s_sum[2][c] + s_sum[3][c]);
        mx = fmaxf(fmaxf(s_max[0][c], s_max[1][c]), fmaxf(s_max[2][c], s_max[3][c]));
        g_pool[b * 256 + c] = sum * (1.f / 256.f);
        g_pool[b * 256 + cCH + c] = mx;
    }
}

// ---------------- 6) final MLP (block per batch) ----------------
__global__ __launch_bounds__(256) void mlp_kernel(const float* __restrict__ x,
                                                  const float* __restrict__ We1, const float* __restrict__ be1,
                                                  const float* __restrict__ We2, const float* __restrict__ be2,
                                                  const float* __restrict__ We3, const float* __restrict__ be3,
                                                  float* __restrict__ out) {
    __shared__ float s_z[cXD + 256];
    __shared__ float s_h1[256];
    __shared__ float s_h2[32];
    const int b = blockIdx.x, t = threadIdx.x;
    for (int i = t; i < cXD; i += 256) s_z[i] = x[b * cXD + i];
    s_z[cXD + t] = g_pool[b * 256 + t];
    __syncthreads();
    {
        float a0 = 0.f, a1 = 0.f, a2 = 0.f, a3 = 0.f;
#pragma unroll 2
        for (int k = 0; k < cXD + 256; k += 4) {
            a0 += s_z[k + 0] * We1[(k + 0) * 256 + t];
            a1 += s_z[k + 1] * We1[(k + 1) * 256 + t];
            a2 += s_z[k + 2] * We1[(k + 2) * 256 + t];
            a3 += s_z[k + 3] * We1[(k + 3) * 256 + t];
        }
        float v = (a0 + a1) + (a2 + a3) + be1[t];
        s_h1[t] = leaky(v);
    }
    __syncthreads();
    if (t < 32) {
        float c0 = 0.f, c1 = 0.f, c2 = 0.f, c3 = 0.f;
        for (int k = 0; k < 256; k += 4) {
            c0 += s_h1[k + 0] * We2[(k + 0) * 32 + t];
            c1 += s_h1[k + 1] * We2[(k + 1) * 32 + t];
            c2 += s_h1[k + 2] * We2[(k + 2) * 32 + t];
            c3 += s_h1[k + 3] * We2[(k + 3) * 32 + t];
        }
        float u = (c0 + c1) + (c2 + c3) + be2[t];
        s_h2[t] = leaky(u);
    }
    __syncthreads();
    if (t < 32) {
        float p = s_h2[t] * We3[t];
#pragma unroll
        for (int o = 16; o; o >>= 1) p += __shfl_xor_sync(0xffffffffu, p, o);
        if (t == 0) out[b] = p + be3[0];
    }
}

// ---------------- launch ----------------
extern "C" void kernel_launch(void* const* d_in, const int* in_sizes, int n_in,
                              void* d_out, int out_size) {
    const float* x       = (const float*)d_in[0];
    const float* y_atoms = (const float*)d_in[1];
    const int*   y_bonds = (const int*)d_in[2];
    const float* W1 = (const float*)d_in[3];
    const float* b1 = (const float*)d_in[4];
    const float* a1 = (const float*)d_in[5];
    const float* W2 = (const float*)d_in[6];
    const float* b2 = (const float*)d_in[7];
    const float* a2 = (const float*)d_in[8];
    const float* W3 = (const float*)d_in[9];
    const float* b3 = (const float*)d_in[10];
    const float* a3 = (const float*)d_in[11];
    const float* We1 = (const float*)d_in[12];
    const float* be1 = (const float*)d_in[13];
    const float* We2 = (const float*)d_in[14];
    const float* be2 = (const float*)d_in[15];
    const float* We3 = (const float*)d_in[16];
    const float* be3 = (const float*)d_in[17];
    float* out = (float*)d_out;

    cudaFuncSetAttribute((const void*)attn_part_kernel<true>,
                         cudaFuncAttributeMaxDynamicSharedMemorySize, ATTN_SMEM);
    cudaFuncSetAttribute((const void*)attn_part_kernel<false>,
                         cudaFuncAttributeMaxDynamicSharedMemorySize, ATTN_SMEM);

    float* atoms_ptr = nullptr;
    cudaGetSymbolAddress((void**)&atoms_ptr, g_atoms);

    const dim3 gemm_grid(10, 128);
    const int attn_grid = cB * N_ITILES * 4;   // 1024 quarter-blocks

    pack_mask_kernel<<<(cB * cN * MASK_WORDS_PER_ROW + 255) / 256, 256>>>(y_bonds);

    // layer 1
    gemm_bias_kernel<cCIN><<<gemm_grid, 256>>>(y_atoms, W1, b1);
    src_dst_kernel<<<cB * cN, 160>>>(a1);
    attn_part_kernel<true><<<attn_grid, 256, ATTN_SMEM>>>();
    // layer 2
    gemm_bias_kernel<cCH><<<gemm_grid, 256>>>(atoms_ptr, W2, b2);
    src_dst_kernel<<<cB * cN, 160>>>(a2);
    attn_part_kernel<true><<<attn_grid, 256, ATTN_SMEM>>>();
    // layer 3
    gemm_bias_kernel<cCH><<<gemm_grid, 256>>>(atoms_ptr, W3, b3);
    src_dst_kernel<<<cB * cN, 160>>>(a3);
    attn_part_kernel<false><<<attn_grid, 256, ATTN_SMEM>>>();

    pool_kernel<<<cB, 512>>>();
    mlp_kernel<<<cB, 256>>>(x, We1, be1, We2, be2, We3, be3, out);
}